// round 3
// baseline (speedup 1.0000x reference)
#include <cuda_runtime.h>
#include <math.h>

#define POI   5000
#define EMB   256
#define UNITS 512
#define QDIM  256
#define BATCH 64
#define X1DIM  (EMB + QDIM)        // 512
#define CATDIM (EMB + 2 * UNITS)   // 1280

// ---------------- scratch (no cudaMalloc allowed) ----------------
__device__ float g_x1[BATCH * X1DIM];
__device__ float g_xm[BATCH * 3 * UNITS];
__device__ float g_hm[BATCH * 3 * UNITS];
__device__ float g_h[BATCH * UNITS];
__device__ float g_qproj[BATCH * UNITS];
__device__ float g_vproj[POI * UNITS];           // 10.24 MB
__device__ float g_score[BATCH * POI];
__device__ float g_outcat[BATCH * CATDIM];

// Accurate tanh via exp identity: tanh(x) = 1 - 2/(exp(2x)+1). __expf rel err ~2^-22.
// Saturates correctly (__fdividef(2, huge/inf) -> 0 -> tanh = 1; exp(-big)->0 -> -1).
__device__ __forceinline__ float tanh_acc(float x) {
    float e = __expf(2.0f * x);
    return 1.0f - __fdividef(2.0f, e + 1.0f);
}

// ---------------- x1 = concat(emb[x], query) ----------------
__global__ void build_x1_kernel(const int* __restrict__ x,
                                const float* __restrict__ query,
                                const float* __restrict__ emb,
                                float* __restrict__ x1) {
    int b = blockIdx.x;
    int u = threadIdx.x;               // 512
    float v = (u < EMB) ? emb[x[b] * EMB + u] : query[b * QDIM + (u - EMB)];
    x1[b * X1DIM + u] = v;
}

// ---------------- generic tiled fp32 GEMM: C = A[MxK] @ W[KxN] + bias ----------------
template <int BM, int BN, int BK, int TM, int TN>
__global__ void gemm_bias_kernel(const float* __restrict__ A,
                                 const float* __restrict__ W,
                                 const float* __restrict__ bias,
                                 float* __restrict__ C,
                                 int M, int N, int K) {
    __shared__ float As[BK][BM + 1];
    __shared__ float Ws[BK][BN];
    const int tx = threadIdx.x;        // BN/TN
    const int ty = threadIdx.y;        // BM/TM
    const int tid = ty * (BN / TN) + tx;
    constexpr int NTH = (BM / TM) * (BN / TN);
    const int m0 = blockIdx.y * BM;
    const int n0 = blockIdx.x * BN;

    float acc[TM][TN];
#pragma unroll
    for (int i = 0; i < TM; i++)
#pragma unroll
        for (int j = 0; j < TN; j++) acc[i][j] = 0.f;

    for (int k0 = 0; k0 < K; k0 += BK) {
#pragma unroll
        for (int t = tid; t < BM * BK; t += NTH) {
            int i = t / BK, j = t % BK;
            int m = m0 + i;
            As[j][i] = (m < M) ? A[m * K + k0 + j] : 0.f;
        }
#pragma unroll
        for (int t = tid; t < BK * BN; t += NTH) {
            int i = t / BN, j = t % BN;
            int n = n0 + j;
            Ws[i][j] = (n < N) ? W[(k0 + i) * N + n] : 0.f;
        }
        __syncthreads();
#pragma unroll
        for (int k = 0; k < BK; ++k) {
            float a[TM], b[TN];
#pragma unroll
            for (int i = 0; i < TM; i++) a[i] = As[k][ty * TM + i];
#pragma unroll
            for (int j = 0; j < TN; j++) b[j] = Ws[k][tx * TN + j];
#pragma unroll
            for (int i = 0; i < TM; i++)
#pragma unroll
                for (int j = 0; j < TN; j++) acc[i][j] = fmaf(a[i], b[j], acc[i][j]);
        }
        __syncthreads();
    }

#pragma unroll
    for (int i = 0; i < TM; i++) {
        int m = m0 + ty * TM + i;
        if (m >= M) break;
#pragma unroll
        for (int j = 0; j < TN; j++) {
            int n = n0 + tx * TN + j;
            if (n < N) C[m * N + n] = acc[i][j] + (bias ? bias[n] : 0.f);
        }
    }
}

// ---------------- GRU gates (keras reset_after=True, order z,r,h) ----------------
__global__ void gru_gates_kernel(const float* __restrict__ xm,
                                 const float* __restrict__ hm,
                                 const float* __restrict__ h_in,
                                 float* __restrict__ h_scratch,
                                 float* __restrict__ out_state,
                                 float* __restrict__ out_output) {
    int b = blockIdx.x;
    int u = threadIdx.x;               // 512
    int base = b * 3 * UNITS;
    float xz = xm[base + u];
    float xr = xm[base + UNITS + u];
    float xh = xm[base + 2 * UNITS + u];
    float hz = hm[base + u];
    float hr = hm[base + UNITS + u];
    float hh = hm[base + 2 * UNITS + u];
    float z = 1.f / (1.f + expf(-(xz + hz)));
    float r = 1.f / (1.f + expf(-(xr + hr)));
    float hc = tanhf(xh + r * hh);
    float h = h_in[b * UNITS + u];
    float hn = z * h + (1.f - z) * hc;
    h_scratch[b * UNITS + u] = hn;
    if (out_state)  out_state[b * UNITS + u] = hn;
    if (out_output) out_output[b * UNITS + u] = hn;
}

// ---------------- attention score (rewritten, 1 batch row per block) ----------------
// grid (ceil(POI/128), BATCH), block 128. Thread tid handles p = p0+tid.
__global__ void attn_score_kernel(const float* __restrict__ vproj,
                                  const float* __restrict__ qproj,
                                  const float* __restrict__ Vw,
                                  const float* __restrict__ Vb,
                                  float* __restrict__ score) {
    __shared__ float q_s[UNITS];       // 2 KB
    __shared__ float vw_s[UNITS];      // 2 KB
    __shared__ float v_s[128][33];     // 16.9 KB, padded
    const int tid = threadIdx.x;       // 128
    const int p0 = blockIdx.x * 128;
    const int b  = blockIdx.y;

    for (int t = tid; t < UNITS; t += 128) {
        q_s[t]  = qproj[b * UNITS + t];
        vw_s[t] = Vw[t];
    }

    float acc = 0.f;
    for (int u0 = 0; u0 < UNITS; u0 += 32) {
        __syncthreads();               // also covers q_s/vw_s on first iter
        for (int t = tid; t < 128 * 32; t += 128) {
            int p = t >> 5, j = t & 31;
            v_s[p][j] = (p0 + p < POI) ? vproj[(p0 + p) * UNITS + u0 + j] : 0.f;
        }
        __syncthreads();
#pragma unroll
        for (int j = 0; j < 32; ++j)
            acc = fmaf(vw_s[u0 + j], tanh_acc(v_s[tid][j] + q_s[u0 + j]), acc);
    }
    if (p0 + tid < POI)
        score[b * POI + p0 + tid] = acc + Vb[0];
}

// ---------------- softmax over POI per batch row (in place) ----------------
__global__ void softmax_rows_kernel(float* __restrict__ score) {
    int b = blockIdx.x;
    int tid = threadIdx.x;             // 256
    __shared__ float red[256];
    float m = -1e30f;
    for (int p = tid; p < POI; p += 256) m = fmaxf(m, score[b * POI + p]);
    red[tid] = m;
    __syncthreads();
    for (int s = 128; s > 0; s >>= 1) {
        if (tid < s) red[tid] = fmaxf(red[tid], red[tid + s]);
        __syncthreads();
    }
    m = red[0];
    __syncthreads();
    float sum = 0.f;
    for (int p = tid; p < POI; p += 256) {
        float e = __expf(score[b * POI + p] - m);
        score[b * POI + p] = e;
        sum += e;
    }
    red[tid] = sum;
    __syncthreads();
    for (int s = 128; s > 0; s >>= 1) {
        if (tid < s) red[tid] += red[tid + s];
        __syncthreads();
    }
    float inv = 1.f / red[0];
    for (int p = tid; p < POI; p += 256) score[b * POI + p] *= inv;
}

// ---------------- context + outcat (rewritten, single simple kernel) ----------------
// grid (BATCH), block 256 (one e per thread). outcat = [context | h | cat_dec]
__global__ void context_outcat_kernel(const float* __restrict__ attn,
                                      const float* __restrict__ emb,
                                      const float* __restrict__ h,
                                      const float* __restrict__ cat_dec,
                                      float* __restrict__ outcat) {
    int b = blockIdx.x;
    int e = threadIdx.x;               // 256 == EMB
    const float* arow = attn + b * POI;
    float acc = 0.f;
#pragma unroll 4
    for (int p = 0; p < POI; ++p)
        acc = fmaf(arow[p], emb[p * EMB + e], acc);
    outcat[b * CATDIM + e] = acc;
    for (int c = e; c < UNITS; c += 256) {
        outcat[b * CATDIM + EMB + c]         = h[b * UNITS + c];
        outcat[b * CATDIM + EMB + UNITS + c] = cat_dec[b * UNITS + c];
    }
}

// ---------------- launch ----------------
extern "C" void kernel_launch(void* const* d_in, const int* in_sizes, int n_in,
                              void* d_out, int out_size) {
    const int*   x          = (const int*)  d_in[0];
    const float* query      = (const float*)d_in[1];
    const float* emb        = (const float*)d_in[2];
    // d_in[3] = A_hat (unused)
    const float* dec_hidden = (const float*)d_in[4];
    const float* cat_dec    = (const float*)d_in[5];   // (1,B,U)
    const float* gru_kernel = (const float*)d_in[6];
    const float* gru_rec    = (const float*)d_in[7];
    const float* gru_bias   = (const float*)d_in[8];
    const float* W1_w       = (const float*)d_in[9];
    const float* W1_b       = (const float*)d_in[10];
    const float* W2_w       = (const float*)d_in[11];
    const float* W2_b       = (const float*)d_in[12];
    const float* V_w        = (const float*)d_in[13];
    const float* V_b        = (const float*)d_in[14];
    const float* fc_w       = (const float*)d_in[15];
    const float* fc_b       = (const float*)d_in[16];

    float* out        = (float*)d_out;
    float* out_logits = out;                              // [64,5000]
    // Derive optional output regions from out_size (defensive vs layout variants).
    float* out_state  = (out_size >= BATCH * POI + BATCH * UNITS)
                        ? out + BATCH * POI : nullptr;
    float* out_output = (out_size >= BATCH * POI + 2 * BATCH * UNITS)
                        ? out + BATCH * POI + BATCH * UNITS : nullptr;

    float *g_x1_p, *g_xm_p, *g_hm_p, *g_h_p, *g_qp_p, *g_vp_p, *g_sc_p, *g_oc_p;
    cudaGetSymbolAddress((void**)&g_x1_p, g_x1);
    cudaGetSymbolAddress((void**)&g_xm_p, g_xm);
    cudaGetSymbolAddress((void**)&g_hm_p, g_hm);
    cudaGetSymbolAddress((void**)&g_h_p,  g_h);
    cudaGetSymbolAddress((void**)&g_qp_p, g_qproj);
    cudaGetSymbolAddress((void**)&g_vp_p, g_vproj);
    cudaGetSymbolAddress((void**)&g_sc_p, g_score);
    cudaGetSymbolAddress((void**)&g_oc_p, g_outcat);

    dim3 gblk(16, 16);

    // v_proj = emb @ W1 + b  (independent of GRU; launch first)
    gemm_bias_kernel<64, 64, 16, 4, 4><<<dim3((UNITS + 63) / 64, (POI + 63) / 64), gblk>>>(
        emb, W1_w, W1_b, g_vp_p, POI, UNITS, EMB);

    // GRU
    build_x1_kernel<<<BATCH, X1DIM>>>(x, query, emb, g_x1_p);
    gemm_bias_kernel<64, 64, 16, 4, 4><<<dim3((3 * UNITS + 63) / 64, 1), gblk>>>(
        g_x1_p, gru_kernel, gru_bias, g_xm_p, BATCH, 3 * UNITS, X1DIM);
    gemm_bias_kernel<64, 64, 16, 4, 4><<<dim3((3 * UNITS + 63) / 64, 1), gblk>>>(
        dec_hidden, gru_rec, gru_bias + 3 * UNITS, g_hm_p, BATCH, 3 * UNITS, UNITS);
    gru_gates_kernel<<<BATCH, UNITS>>>(g_xm_p, g_hm_p, dec_hidden,
                                       g_h_p, out_state, out_output);

    // q_proj = h_new @ W2 + b
    gemm_bias_kernel<64, 64, 16, 4, 4><<<dim3((UNITS + 63) / 64, 1), gblk>>>(
        g_h_p, W2_w, W2_b, g_qp_p, BATCH, UNITS, UNITS);

    // attention (rewritten path)
    attn_score_kernel<<<dim3((POI + 127) / 128, BATCH), 128>>>(
        g_vp_p, g_qp_p, V_w, V_b, g_sc_p);
    softmax_rows_kernel<<<BATCH, 256>>>(g_sc_p);
    context_outcat_kernel<<<BATCH, 256>>>(g_sc_p, emb, g_h_p, cat_dec, g_oc_p);

    // final dense
    gemm_bias_kernel<64, 64, 16, 4, 4><<<dim3((POI + 63) / 64, 1), gblk>>>(
        g_oc_p, fc_w, fc_b, out_logits, BATCH, POI, CATDIM);
}

// round 4
// speedup vs baseline: 2.3711x; 2.3711x over previous
#include <cuda_runtime.h>
#include <math.h>

#define POI   5000
#define EMB   256
#define UNITS 512
#define QDIM  256
#define BATCH 64
#define X1DIM  (EMB + QDIM)        // 512
#define CATDIM (EMB + 2 * UNITS)   // 1280
#define NCH    10                  // context p-chunks (5000/10 = 500)

// ---------------- scratch (no cudaMalloc allowed) ----------------
__device__ float g_x1[BATCH * X1DIM];
__device__ float g_xm[BATCH * 3 * UNITS];
__device__ float g_hm[BATCH * 3 * UNITS];
__device__ float g_h[BATCH * UNITS];
__device__ float g_qproj[BATCH * UNITS];
__device__ float g_vproj[POI * UNITS];            // 10.24 MB
__device__ float g_score[BATCH * POI];
__device__ float g_ctxpart[NCH * BATCH * EMB];
__device__ float g_outcat[BATCH * CATDIM];
__device__ float g_part[5 * BATCH * POI];         // K-split partials (max: fc, 6.4MB)

// MUFU tanh: measured (R1 vs R2) contribution to final rel_err <= ~8e-5. Safe.
__device__ __forceinline__ float tanh_ap(float x) {
    float y;
    asm("tanh.approx.f32 %0, %1;" : "=f"(y) : "f"(x));
    return y;
}

// ---------------- x1 = concat(emb[x], query) ----------------
__global__ void build_x1_kernel(const int* __restrict__ x,
                                const float* __restrict__ query,
                                const float* __restrict__ emb,
                                float* __restrict__ x1) {
    int b = blockIdx.x;
    int u = threadIdx.x;               // 512
    float v = (u < EMB) ? emb[x[b] * EMB + u] : query[b * QDIM + (u - EMB)];
    x1[b * X1DIM + u] = v;
}

// ---------------- gemm64: C[M,N] = A[M,K] @ W[K,N] (+bias if gridDim.z==1) --------
// grid (N/64, ceil(M/64), S). Each z-slice computes a K-chunk of kchunk (multiple
// of 64) and writes either C directly (S==1, with bias) or a partial slab.
// block = 256 threads. Requires K % 64 == 0, N % 4 == 0.
__global__ void gemm64_kernel(const float* __restrict__ A,
                              const float* __restrict__ W,
                              const float* __restrict__ bias,
                              float* __restrict__ out,
                              int M, int N, int K, int kchunk) {
    __shared__ float As[64][65];       // As[k][m], padded (scalar reads)
    __shared__ float Ws[64][64];       // Ws[k][n]
    const int tid = threadIdx.x;
    const int r = tid >> 4;            // 0..15
    const int c = tid & 15;            // 0..15
    const int n0 = blockIdx.x * 64;
    const int m0 = blockIdx.y * 64;
    const int kbase = blockIdx.z * kchunk;

    float acc[4][4];
#pragma unroll
    for (int i = 0; i < 4; i++)
#pragma unroll
        for (int j = 0; j < 4; j++) acc[i][j] = 0.f;

    for (int kk = kbase; kk < kbase + kchunk; kk += 64) {
        // A tile (transposed into As[k][m])
#pragma unroll
        for (int i = 0; i < 4; i++) {
            int m = m0 + r + i * 16;
            float4 v = make_float4(0.f, 0.f, 0.f, 0.f);
            if (m < M) v = *(const float4*)(A + (size_t)m * K + kk + c * 4);
            As[c * 4 + 0][r + i * 16] = v.x;
            As[c * 4 + 1][r + i * 16] = v.y;
            As[c * 4 + 2][r + i * 16] = v.z;
            As[c * 4 + 3][r + i * 16] = v.w;
        }
        // W tile (direct)
#pragma unroll
        for (int i = 0; i < 4; i++) {
            int k = r + i * 16;
            int n = n0 + c * 4;
            float4 v = make_float4(0.f, 0.f, 0.f, 0.f);
            if (n < N) v = *(const float4*)(W + (size_t)(kk + k) * N + n);
            *(float4*)&Ws[k][c * 4] = v;
        }
        __syncthreads();
#pragma unroll
        for (int k = 0; k < 64; k++) {
            float a0 = As[k][r * 4 + 0];
            float a1 = As[k][r * 4 + 1];
            float a2 = As[k][r * 4 + 2];
            float a3 = As[k][r * 4 + 3];
            float4 b = *(const float4*)&Ws[k][c * 4];
            acc[0][0] = fmaf(a0, b.x, acc[0][0]); acc[0][1] = fmaf(a0, b.y, acc[0][1]);
            acc[0][2] = fmaf(a0, b.z, acc[0][2]); acc[0][3] = fmaf(a0, b.w, acc[0][3]);
            acc[1][0] = fmaf(a1, b.x, acc[1][0]); acc[1][1] = fmaf(a1, b.y, acc[1][1]);
            acc[1][2] = fmaf(a1, b.z, acc[1][2]); acc[1][3] = fmaf(a1, b.w, acc[1][3]);
            acc[2][0] = fmaf(a2, b.x, acc[2][0]); acc[2][1] = fmaf(a2, b.y, acc[2][1]);
            acc[2][2] = fmaf(a2, b.z, acc[2][2]); acc[2][3] = fmaf(a2, b.w, acc[2][3]);
            acc[3][0] = fmaf(a3, b.x, acc[3][0]); acc[3][1] = fmaf(a3, b.y, acc[3][1]);
            acc[3][2] = fmaf(a3, b.z, acc[3][2]); acc[3][3] = fmaf(a3, b.w, acc[3][3]);
        }
        __syncthreads();
    }

    const bool direct = (gridDim.z == 1);
    float* dst = direct ? out : out + (size_t)blockIdx.z * M * N;
#pragma unroll
    for (int i = 0; i < 4; i++) {
        int m = m0 + r * 4 + i;
        if (m >= M) continue;
#pragma unroll
        for (int j = 0; j < 4; j++) {
            int n = n0 + c * 4 + j;
            if (n < N)
                dst[(size_t)m * N + n] = acc[i][j] + (direct ? bias[n] : 0.f);
        }
    }
}

// ---------------- reduce K-split partials + bias ----------------
__global__ void reduce_bias_kernel(const float* __restrict__ part,
                                   const float* __restrict__ bias,
                                   float* __restrict__ C,
                                   int MN, int N, int S) {
    int i = blockIdx.x * 256 + threadIdx.x;
    if (i >= MN) return;
    float s = 0.f;
    for (int z = 0; z < S; z++) s += part[(size_t)z * MN + i];
    C[i] = s + bias[i % N];
}

// ---------------- GRU gates (keras reset_after=True, order z,r,h) ----------------
__global__ void gru_gates_kernel(const float* __restrict__ xm,
                                 const float* __restrict__ hm,
                                 const float* __restrict__ h_in,
                                 float* __restrict__ h_scratch,
                                 float* __restrict__ out_state,
                                 float* __restrict__ out_output) {
    int b = blockIdx.x;
    int u = threadIdx.x;               // 512
    int base = b * 3 * UNITS;
    float xz = xm[base + u];
    float xr = xm[base + UNITS + u];
    float xh = xm[base + 2 * UNITS + u];
    float hz = hm[base + u];
    float hr = hm[base + UNITS + u];
    float hh = hm[base + 2 * UNITS + u];
    float z = 1.f / (1.f + expf(-(xz + hz)));
    float r = 1.f / (1.f + expf(-(xr + hr)));
    float hc = tanhf(xh + r * hh);
    float h = h_in[b * UNITS + u];
    float hn = z * h + (1.f - z) * hc;
    h_scratch[b * UNITS + u] = hn;
    if (out_state)  out_state[b * UNITS + u] = hn;
    if (out_output) out_output[b * UNITS + u] = hn;
}

// ---------------- attention score (proven round-3 structure, MUFU tanh) ----------
// grid (ceil(POI/128), BATCH), block 128.
__global__ void attn_score_kernel(const float* __restrict__ vproj,
                                  const float* __restrict__ qproj,
                                  const float* __restrict__ Vw,
                                  const float* __restrict__ Vb,
                                  float* __restrict__ score) {
    __shared__ float q_s[UNITS];
    __shared__ float vw_s[UNITS];
    __shared__ float v_s[128][33];
    const int tid = threadIdx.x;       // 128
    const int p0 = blockIdx.x * 128;
    const int b  = blockIdx.y;

    for (int t = tid; t < UNITS; t += 128) {
        q_s[t]  = qproj[b * UNITS + t];
        vw_s[t] = Vw[t];
    }

    float acc = 0.f;
    for (int u0 = 0; u0 < UNITS; u0 += 32) {
        __syncthreads();               // also covers q_s/vw_s on first iter
        for (int t = tid; t < 128 * 32; t += 128) {
            int p = t >> 5, j = t & 31;
            v_s[p][j] = (p0 + p < POI) ? vproj[(p0 + p) * UNITS + u0 + j] : 0.f;
        }
        __syncthreads();
#pragma unroll
        for (int j = 0; j < 32; ++j)
            acc = fmaf(vw_s[u0 + j], tanh_ap(v_s[tid][j] + q_s[u0 + j]), acc);
    }
    if (p0 + tid < POI)
        score[b * POI + p0 + tid] = acc + Vb[0];
}

// ---------------- softmax over POI per batch row (in place) ----------------
__global__ void softmax_rows_kernel(float* __restrict__ score) {
    int b = blockIdx.x;
    int tid = threadIdx.x;             // 256
    __shared__ float red[256];
    float m = -1e30f;
    for (int p = tid; p < POI; p += 256) m = fmaxf(m, score[b * POI + p]);
    red[tid] = m;
    __syncthreads();
    for (int s = 128; s > 0; s >>= 1) {
        if (tid < s) red[tid] = fmaxf(red[tid], red[tid + s]);
        __syncthreads();
    }
    m = red[0];
    __syncthreads();
    float sum = 0.f;
    for (int p = tid; p < POI; p += 256) {
        float e = __expf(score[b * POI + p] - m);
        score[b * POI + p] = e;
        sum += e;
    }
    red[tid] = sum;
    __syncthreads();
    for (int s = 128; s > 0; s >>= 1) {
        if (tid < s) red[tid] += red[tid + s];
        __syncthreads();
    }
    float inv = 1.f / red[0];
    for (int p = tid; p < POI; p += 256) score[b * POI + p] *= inv;
}

// ---------------- context partials: 4 batch rows per block, NCH p-chunks --------
// grid (BATCH/4, NCH), block 256 (e).
__global__ void context_partial_kernel(const float* __restrict__ attn,
                                       const float* __restrict__ emb,
                                       float* __restrict__ part) {
    const int PC = POI / NCH;          // 500
    int b0 = blockIdx.x * 4;
    int ch = blockIdx.y;
    int e  = threadIdx.x;              // 256 == EMB
    int p0 = ch * PC;
    const float* a0 = attn + (b0 + 0) * POI;
    const float* a1 = attn + (b0 + 1) * POI;
    const float* a2 = attn + (b0 + 2) * POI;
    const float* a3 = attn + (b0 + 3) * POI;
    float c0 = 0.f, c1 = 0.f, c2 = 0.f, c3 = 0.f;
#pragma unroll 4
    for (int p = p0; p < p0 + PC; ++p) {
        float ev = emb[p * EMB + e];
        c0 = fmaf(a0[p], ev, c0);
        c1 = fmaf(a1[p], ev, c1);
        c2 = fmaf(a2[p], ev, c2);
        c3 = fmaf(a3[p], ev, c3);
    }
    part[(ch * BATCH + b0 + 0) * EMB + e] = c0;
    part[(ch * BATCH + b0 + 1) * EMB + e] = c1;
    part[(ch * BATCH + b0 + 2) * EMB + e] = c2;
    part[(ch * BATCH + b0 + 3) * EMB + e] = c3;
}

// ---------------- outcat = [sum(ctx partials) | h | cat_dec] ----------------
__global__ void build_outcat_kernel(const float* __restrict__ part,
                                    const float* __restrict__ h,
                                    const float* __restrict__ cat_dec,
                                    float* __restrict__ outcat) {
    int b = blockIdx.x;
    int e = threadIdx.x;               // 256
    float s = 0.f;
#pragma unroll
    for (int ch = 0; ch < NCH; ch++) s += part[(ch * BATCH + b) * EMB + e];
    outcat[b * CATDIM + e] = s;
    for (int c = e; c < UNITS; c += 256) {
        outcat[b * CATDIM + EMB + c]         = h[b * UNITS + c];
        outcat[b * CATDIM + EMB + UNITS + c] = cat_dec[b * UNITS + c];
    }
}

// ---------------- launch ----------------
extern "C" void kernel_launch(void* const* d_in, const int* in_sizes, int n_in,
                              void* d_out, int out_size) {
    const int*   x          = (const int*)  d_in[0];
    const float* query      = (const float*)d_in[1];
    const float* emb        = (const float*)d_in[2];
    // d_in[3] = A_hat (unused)
    const float* dec_hidden = (const float*)d_in[4];
    const float* cat_dec    = (const float*)d_in[5];
    const float* gru_kernel = (const float*)d_in[6];
    const float* gru_rec    = (const float*)d_in[7];
    const float* gru_bias   = (const float*)d_in[8];
    const float* W1_w       = (const float*)d_in[9];
    const float* W1_b       = (const float*)d_in[10];
    const float* W2_w       = (const float*)d_in[11];
    const float* W2_b       = (const float*)d_in[12];
    const float* V_w        = (const float*)d_in[13];
    const float* V_b        = (const float*)d_in[14];
    const float* fc_w       = (const float*)d_in[15];
    const float* fc_b       = (const float*)d_in[16];

    float* out        = (float*)d_out;
    float* out_logits = out;
    float* out_state  = (out_size >= BATCH * POI + BATCH * UNITS)
                        ? out + BATCH * POI : nullptr;
    float* out_output = (out_size >= BATCH * POI + 2 * BATCH * UNITS)
                        ? out + BATCH * POI + BATCH * UNITS : nullptr;

    float *g_x1_p, *g_xm_p, *g_hm_p, *g_h_p, *g_qp_p, *g_vp_p, *g_sc_p, *g_cp_p, *g_oc_p, *g_pt_p;
    cudaGetSymbolAddress((void**)&g_x1_p, g_x1);
    cudaGetSymbolAddress((void**)&g_xm_p, g_xm);
    cudaGetSymbolAddress((void**)&g_hm_p, g_hm);
    cudaGetSymbolAddress((void**)&g_h_p,  g_h);
    cudaGetSymbolAddress((void**)&g_qp_p, g_qproj);
    cudaGetSymbolAddress((void**)&g_vp_p, g_vproj);
    cudaGetSymbolAddress((void**)&g_sc_p, g_score);
    cudaGetSymbolAddress((void**)&g_cp_p, g_ctxpart);
    cudaGetSymbolAddress((void**)&g_oc_p, g_outcat);
    cudaGetSymbolAddress((void**)&g_pt_p, g_part);

    // v_proj = emb @ W1 + b : M=5000, N=512, K=256 (direct, S=1)
    gemm64_kernel<<<dim3(UNITS / 64, (POI + 63) / 64, 1), 256>>>(
        emb, W1_w, W1_b, g_vp_p, POI, UNITS, EMB, 256);

    // x1 then xm = x1 @ gru_kernel + bias[0] : K=512 split 8
    build_x1_kernel<<<BATCH, X1DIM>>>(x, query, emb, g_x1_p);
    gemm64_kernel<<<dim3(3 * UNITS / 64, 1, 8), 256>>>(
        g_x1_p, gru_kernel, nullptr, g_pt_p, BATCH, 3 * UNITS, X1DIM, 64);
    reduce_bias_kernel<<<(BATCH * 3 * UNITS + 255) / 256, 256>>>(
        g_pt_p, gru_bias, g_xm_p, BATCH * 3 * UNITS, 3 * UNITS, 8);

    // hm = dec_hidden @ gru_rec + bias[1]
    gemm64_kernel<<<dim3(3 * UNITS / 64, 1, 8), 256>>>(
        dec_hidden, gru_rec, nullptr, g_pt_p, BATCH, 3 * UNITS, UNITS, 64);
    reduce_bias_kernel<<<(BATCH * 3 * UNITS + 255) / 256, 256>>>(
        g_pt_p, gru_bias + 3 * UNITS, g_hm_p, BATCH * 3 * UNITS, 3 * UNITS, 8);

    gru_gates_kernel<<<BATCH, UNITS>>>(g_xm_p, g_hm_p, dec_hidden,
                                       g_h_p, out_state, out_output);

    // q_proj = h @ W2 + b : N=512, K=512 split 8
    gemm64_kernel<<<dim3(UNITS / 64, 1, 8), 256>>>(
        g_h_p, W2_w, nullptr, g_pt_p, BATCH, UNITS, UNITS, 64);
    reduce_bias_kernel<<<(BATCH * UNITS + 255) / 256, 256>>>(
        g_pt_p, W2_b, g_qp_p, BATCH * UNITS, UNITS, 8);

    // attention
    attn_score_kernel<<<dim3((POI + 127) / 128, BATCH), 128>>>(
        g_vp_p, g_qp_p, V_w, V_b, g_sc_p);
    softmax_rows_kernel<<<BATCH, 256>>>(g_sc_p);
    context_partial_kernel<<<dim3(BATCH / 4, NCH), 256>>>(g_sc_p, emb, g_cp_p);
    build_outcat_kernel<<<BATCH, 256>>>(g_cp_p, g_h_p, cat_dec, g_oc_p);

    // logits = outcat @ fc_w + fc_b : N=5000, K=1280 split 5
    gemm64_kernel<<<dim3((POI + 63) / 64, 1, 5), 256>>>(
        g_oc_p, fc_w, nullptr, g_pt_p, BATCH, POI, CATDIM, 256);
    reduce_bias_kernel<<<(BATCH * POI + 255) / 256, 256>>>(
        g_pt_p, fc_b, out_logits, BATCH * POI, POI, 5);
}

// round 5
// speedup vs baseline: 3.6861x; 1.5546x over previous
#include <cuda_runtime.h>
#include <math.h>

#define POI   5000
#define EMB   256
#define UNITS 512
#define QDIM  256
#define BATCH 64
#define X1DIM  (EMB + QDIM)        // 512
#define CATDIM (EMB + 2 * UNITS)   // 1280
#define NCH    10                  // context p-chunks (5000/10 = 500)

// ---------------- scratch (no cudaMalloc allowed) ----------------
__device__ float g_x1[BATCH * X1DIM];
__device__ float g_h[BATCH * UNITS];
__device__ float g_qproj[BATCH * UNITS];
__device__ float g_vproj[POI * UNITS];            // 10.24 MB
__device__ float g_score[BATCH * POI];
__device__ float g_ctxpart[NCH * BATCH * EMB];
__device__ float g_outcat[BATCH * CATDIM];
__device__ float g_part[5 * BATCH * POI];         // partial slabs (max 1.6M floats)

__device__ __forceinline__ float tanh_ap(float x) {
    float y;
    asm("tanh.approx.f32 %0, %1;" : "=f"(y) : "f"(x));
    return y;
}

// ---------------- x1 = concat(emb[x], query) ----------------
__global__ void build_x1_kernel(const int* __restrict__ x,
                                const float* __restrict__ query,
                                const float* __restrict__ emb,
                                float* __restrict__ x1) {
    int b = blockIdx.x;
    int u = threadIdx.x;               // 512
    float v = (u < EMB) ? emb[x[b] * EMB + u] : query[b * QDIM + (u - EMB)];
    x1[b * X1DIM + u] = v;
}

// ---------------- gemm_v2: C[M,N] = A[M,K] @ W[K,N] (+bias iff gridDim.z==1) -----
// BK=32, block=256 threads = 16(r) x 16(c); thread computes TM x TN.
// Requires BM/TM==16, BN/TN==16, K%32==0, kchunk%32==0, N%4==0, TN%4==0.
// grid (N/BN, ceil(M/BM), S). S>1 -> writes partial slab z (no bias).
template <int BM, int BN, int TM, int TN>
__global__ void gemm_v2_kernel(const float* __restrict__ A,
                               const float* __restrict__ W,
                               const float* __restrict__ bias,
                               float* __restrict__ out,
                               int M, int N, int K, int kchunk) {
    __shared__ float As[32][BM + 1];   // As[k][m], transposed, scalar stores
    __shared__ float Ws[32][BN];       // Ws[k][n]
    const int tid = threadIdx.x;
    const int r = tid >> 4;            // 0..15
    const int c = tid & 15;            // 0..15
    const int n0 = blockIdx.x * BN;
    const int m0 = blockIdx.y * BM;
    const int kbase = blockIdx.z * kchunk;

    float acc[TM][TN];
#pragma unroll
    for (int i = 0; i < TM; i++)
#pragma unroll
        for (int j = 0; j < TN; j++) acc[i][j] = 0.f;

    for (int kk = kbase; kk < kbase + kchunk; kk += 32) {
        // A tile: BM x 32 floats, each thread loads (BM*32/1024) float4s
#pragma unroll
        for (int pass = 0; pass < (BM * 32) / 1024; pass++) {
            int idx = pass * 1024 + tid * 4;
            int m = idx >> 5;          // /32
            int k = idx & 31;
            float4 v = make_float4(0.f, 0.f, 0.f, 0.f);
            if (m0 + m < M) v = *(const float4*)(A + (size_t)(m0 + m) * K + kk + k);
            As[k + 0][m] = v.x;
            As[k + 1][m] = v.y;
            As[k + 2][m] = v.z;
            As[k + 3][m] = v.w;
        }
        // W tile: 32 x BN floats
#pragma unroll
        for (int pass = 0; pass < (32 * BN) / 1024; pass++) {
            int idx = pass * 1024 + tid * 4;
            int k = idx / BN;
            int n = idx % BN;
            float4 v = make_float4(0.f, 0.f, 0.f, 0.f);
            if (n0 + n < N) v = *(const float4*)(W + (size_t)(kk + k) * N + n0 + n);
            *(float4*)&Ws[k][n] = v;
        }
        __syncthreads();
#pragma unroll
        for (int k = 0; k < 32; k++) {
            float a[TM];
#pragma unroll
            for (int i = 0; i < TM; i++) a[i] = As[k][r * TM + i];
            float b[TN];
#pragma unroll
            for (int j = 0; j < TN; j += 4)
                *(float4*)&b[j] = *(const float4*)&Ws[k][c * TN + j];
#pragma unroll
            for (int i = 0; i < TM; i++)
#pragma unroll
                for (int j = 0; j < TN; j++)
                    acc[i][j] = fmaf(a[i], b[j], acc[i][j]);
        }
        __syncthreads();
    }

    const bool direct = (gridDim.z == 1);
    float* dst = direct ? out : out + (size_t)blockIdx.z * M * N;
#pragma unroll
    for (int i = 0; i < TM; i++) {
        int m = m0 + r * TM + i;
        if (m >= M) continue;
#pragma unroll
        for (int j = 0; j < TN; j += 4) {
            int n = n0 + c * TN + j;
            if (n < N) {
                float4 v;
                v.x = acc[i][j + 0] + (direct ? bias[n + 0] : 0.f);
                v.y = acc[i][j + 1] + (direct ? bias[n + 1] : 0.f);
                v.z = acc[i][j + 2] + (direct ? bias[n + 2] : 0.f);
                v.w = acc[i][j + 3] + (direct ? bias[n + 3] : 0.f);
                *(float4*)(dst + (size_t)m * N + n) = v;
            }
        }
    }
}

// ---------------- reduce K-split partials + bias ----------------
__global__ void reduce_bias_kernel(const float* __restrict__ part,
                                   const float* __restrict__ bias,
                                   float* __restrict__ C,
                                   int MN, int N, int S) {
    int i = blockIdx.x * 256 + threadIdx.x;
    if (i >= MN) return;
    float s = 0.f;
    for (int z = 0; z < S; z++) s += part[(size_t)z * MN + i];
    C[i] = s + bias[i % N];
}

// ---------------- GRU gates: sums 8 xm slabs + 8 hm slabs + bias, applies gates --
// part layout: slabs 0..7 = xm partials [B,1536], slabs 8..15 = hm partials.
__global__ void gru_gates_kernel(const float* __restrict__ part,
                                 const float* __restrict__ bias,
                                 const float* __restrict__ h_in,
                                 float* __restrict__ h_scratch,
                                 float* __restrict__ out_state,
                                 float* __restrict__ out_output) {
    const int NN = 3 * UNITS;
    int b = blockIdx.x;
    int u = threadIdx.x;               // 512
    float xz = bias[u], xr = bias[UNITS + u], xh = bias[2 * UNITS + u];
    float hz = bias[NN + u], hr = bias[NN + UNITS + u], hh = bias[NN + 2 * UNITS + u];
#pragma unroll
    for (int z = 0; z < 8; z++) {
        const float* px = part + (size_t)z * BATCH * NN + b * NN;
        const float* ph = part + (size_t)(8 + z) * BATCH * NN + b * NN;
        xz += px[u]; xr += px[UNITS + u]; xh += px[2 * UNITS + u];
        hz += ph[u]; hr += ph[UNITS + u]; hh += ph[2 * UNITS + u];
    }
    float z = 1.f / (1.f + expf(-(xz + hz)));
    float r = 1.f / (1.f + expf(-(xr + hr)));
    float hc = tanhf(xh + r * hh);
    float h = h_in[b * UNITS + u];
    float hn = z * h + (1.f - z) * hc;
    h_scratch[b * UNITS + u] = hn;
    if (out_state)  out_state[b * UNITS + u] = hn;
    if (out_output) out_output[b * UNITS + u] = hn;
}

// ---------------- attention score, 4 batch rows per block ----------------
// grid (ceil(POI/128), BATCH/4), block 128.
__global__ void attn_score_kernel(const float* __restrict__ vproj,
                                  const float* __restrict__ qproj,
                                  const float* __restrict__ Vw,
                                  const float* __restrict__ Vb,
                                  float* __restrict__ score) {
    __shared__ float q_s[4][UNITS];    // 8 KB
    __shared__ float vw_s[UNITS];      // 2 KB
    __shared__ float v_s[128][33];     // 16.9 KB
    const int tid = threadIdx.x;       // 128
    const int p0 = blockIdx.x * 128;
    const int b0 = blockIdx.y * 4;

    for (int t = tid; t < 4 * UNITS; t += 128) {
        int b = t >> 9, u = t & 511;   // UNITS == 512
        q_s[b][u] = qproj[(b0 + b) * UNITS + u];
    }
    for (int t = tid; t < UNITS; t += 128) vw_s[t] = Vw[t];

    float acc0 = 0.f, acc1 = 0.f, acc2 = 0.f, acc3 = 0.f;
    for (int u0 = 0; u0 < UNITS; u0 += 32) {
        __syncthreads();               // also covers q_s/vw_s on first iter
        for (int t = tid; t < 128 * 32; t += 128) {
            int p = t >> 5, j = t & 31;
            v_s[p][j] = (p0 + p < POI) ? vproj[(p0 + p) * UNITS + u0 + j] : 0.f;
        }
        __syncthreads();
#pragma unroll
        for (int j = 0; j < 32; ++j) {
            float v  = v_s[tid][j];
            float vw = vw_s[u0 + j];
            acc0 = fmaf(vw, tanh_ap(v + q_s[0][u0 + j]), acc0);
            acc1 = fmaf(vw, tanh_ap(v + q_s[1][u0 + j]), acc1);
            acc2 = fmaf(vw, tanh_ap(v + q_s[2][u0 + j]), acc2);
            acc3 = fmaf(vw, tanh_ap(v + q_s[3][u0 + j]), acc3);
        }
    }
    if (p0 + tid < POI) {
        float vb = Vb[0];
        score[(b0 + 0) * POI + p0 + tid] = acc0 + vb;
        score[(b0 + 1) * POI + p0 + tid] = acc1 + vb;
        score[(b0 + 2) * POI + p0 + tid] = acc2 + vb;
        score[(b0 + 3) * POI + p0 + tid] = acc3 + vb;
    }
}

// ---------------- softmax over POI per batch row (in place) ----------------
__global__ void softmax_rows_kernel(float* __restrict__ score) {
    int b = blockIdx.x;
    int tid = threadIdx.x;             // 256
    __shared__ float red[256];
    float m = -1e30f;
    for (int p = tid; p < POI; p += 256) m = fmaxf(m, score[b * POI + p]);
    red[tid] = m;
    __syncthreads();
    for (int s = 128; s > 0; s >>= 1) {
        if (tid < s) red[tid] = fmaxf(red[tid], red[tid + s]);
        __syncthreads();
    }
    m = red[0];
    __syncthreads();
    float sum = 0.f;
    for (int p = tid; p < POI; p += 256) {
        float e = __expf(score[b * POI + p] - m);
        score[b * POI + p] = e;
        sum += e;
    }
    red[tid] = sum;
    __syncthreads();
    for (int s = 128; s > 0; s >>= 1) {
        if (tid < s) red[tid] += red[tid + s];
        __syncthreads();
    }
    float inv = 1.f / red[0];
    for (int p = tid; p < POI; p += 256) score[b * POI + p] *= inv;
}

// ---------------- context partials: 4 batch rows per block, NCH p-chunks --------
__global__ void context_partial_kernel(const float* __restrict__ attn,
                                       const float* __restrict__ emb,
                                       float* __restrict__ part) {
    const int PC = POI / NCH;          // 500
    int b0 = blockIdx.x * 4;
    int ch = blockIdx.y;
    int e  = threadIdx.x;              // 256 == EMB
    int p0 = ch * PC;
    const float* a0 = attn + (b0 + 0) * POI;
    const float* a1 = attn + (b0 + 1) * POI;
    const float* a2 = attn + (b0 + 2) * POI;
    const float* a3 = attn + (b0 + 3) * POI;
    float c0 = 0.f, c1 = 0.f, c2 = 0.f, c3 = 0.f;
#pragma unroll 4
    for (int p = p0; p < p0 + PC; ++p) {
        float ev = emb[p * EMB + e];
        c0 = fmaf(a0[p], ev, c0);
        c1 = fmaf(a1[p], ev, c1);
        c2 = fmaf(a2[p], ev, c2);
        c3 = fmaf(a3[p], ev, c3);
    }
    part[(ch * BATCH + b0 + 0) * EMB + e] = c0;
    part[(ch * BATCH + b0 + 1) * EMB + e] = c1;
    part[(ch * BATCH + b0 + 2) * EMB + e] = c2;
    part[(ch * BATCH + b0 + 3) * EMB + e] = c3;
}

// ---------------- outcat = [sum(ctx partials) | h | cat_dec] ----------------
__global__ void build_outcat_kernel(const float* __restrict__ part,
                                    const float* __restrict__ h,
                                    const float* __restrict__ cat_dec,
                                    float* __restrict__ outcat) {
    int b = blockIdx.x;
    int e = threadIdx.x;               // 256
    float s = 0.f;
#pragma unroll
    for (int ch = 0; ch < NCH; ch++) s += part[(ch * BATCH + b) * EMB + e];
    outcat[b * CATDIM + e] = s;
    for (int c = e; c < UNITS; c += 256) {
        outcat[b * CATDIM + EMB + c]         = h[b * UNITS + c];
        outcat[b * CATDIM + EMB + UNITS + c] = cat_dec[b * UNITS + c];
    }
}

// ---------------- launch ----------------
extern "C" void kernel_launch(void* const* d_in, const int* in_sizes, int n_in,
                              void* d_out, int out_size) {
    const int*   x          = (const int*)  d_in[0];
    const float* query      = (const float*)d_in[1];
    const float* emb        = (const float*)d_in[2];
    // d_in[3] = A_hat (unused)
    const float* dec_hidden = (const float*)d_in[4];
    const float* cat_dec    = (const float*)d_in[5];
    const float* gru_kernel = (const float*)d_in[6];
    const float* gru_rec    = (const float*)d_in[7];
    const float* gru_bias   = (const float*)d_in[8];
    const float* W1_w       = (const float*)d_in[9];
    const float* W1_b       = (const float*)d_in[10];
    const float* W2_w       = (const float*)d_in[11];
    const float* W2_b       = (const float*)d_in[12];
    const float* V_w        = (const float*)d_in[13];
    const float* V_b        = (const float*)d_in[14];
    const float* fc_w       = (const float*)d_in[15];
    const float* fc_b       = (const float*)d_in[16];

    float* out        = (float*)d_out;
    float* out_logits = out;
    float* out_state  = (out_size >= BATCH * POI + BATCH * UNITS)
                        ? out + BATCH * POI : nullptr;
    float* out_output = (out_size >= BATCH * POI + 2 * BATCH * UNITS)
                        ? out + BATCH * POI + BATCH * UNITS : nullptr;

    float *g_x1_p, *g_h_p, *g_qp_p, *g_vp_p, *g_sc_p, *g_cp_p, *g_oc_p, *g_pt_p;
    cudaGetSymbolAddress((void**)&g_x1_p, g_x1);
    cudaGetSymbolAddress((void**)&g_h_p,  g_h);
    cudaGetSymbolAddress((void**)&g_qp_p, g_qproj);
    cudaGetSymbolAddress((void**)&g_vp_p, g_vproj);
    cudaGetSymbolAddress((void**)&g_sc_p, g_score);
    cudaGetSymbolAddress((void**)&g_cp_p, g_ctxpart);
    cudaGetSymbolAddress((void**)&g_oc_p, g_outcat);
    cudaGetSymbolAddress((void**)&g_pt_p, g_part);

    // v_proj = emb @ W1 + b : M=5000, N=512, K=256 (direct)
    gemm_v2_kernel<128, 64, 8, 4><<<dim3(UNITS / 64, (POI + 127) / 128, 1), 256>>>(
        emb, W1_w, W1_b, g_vp_p, POI, UNITS, EMB, EMB);

    // GRU: x1, then xm partials (slabs 0..7) and hm partials (slabs 8..15)
    build_x1_kernel<<<BATCH, X1DIM>>>(x, query, emb, g_x1_p);
    gemm_v2_kernel<64, 64, 4, 4><<<dim3(3 * UNITS / 64, 1, 8), 256>>>(
        g_x1_p, gru_kernel, nullptr, g_pt_p, BATCH, 3 * UNITS, X1DIM, 64);
    gemm_v2_kernel<64, 64, 4, 4><<<dim3(3 * UNITS / 64, 1, 8), 256>>>(
        dec_hidden, gru_rec, nullptr, g_pt_p + (size_t)8 * BATCH * 3 * UNITS,
        BATCH, 3 * UNITS, UNITS, 64);
    gru_gates_kernel<<<BATCH, UNITS>>>(g_pt_p, gru_bias, dec_hidden,
                                       g_h_p, out_state, out_output);

    // q_proj = h @ W2 + b : K=512 split 8 (g_part slabs free again)
    gemm_v2_kernel<64, 64, 4, 4><<<dim3(UNITS / 64, 1, 8), 256>>>(
        g_h_p, W2_w, nullptr, g_pt_p, BATCH, UNITS, UNITS, 64);
    reduce_bias_kernel<<<(BATCH * UNITS + 255) / 256, 256>>>(
        g_pt_p, W2_b, g_qp_p, BATCH * UNITS, UNITS, 8);

    // attention
    attn_score_kernel<<<dim3((POI + 127) / 128, BATCH / 4), 128>>>(
        g_vp_p, g_qp_p, V_w, V_b, g_sc_p);
    softmax_rows_kernel<<<BATCH, 256>>>(g_sc_p);
    context_partial_kernel<<<dim3(BATCH / 4, NCH), 256>>>(g_sc_p, emb, g_cp_p);
    build_outcat_kernel<<<BATCH, 256>>>(g_cp_p, g_h_p, cat_dec, g_oc_p);

    // logits = outcat @ fc_w + fc_b : N=5000, K=1280 split 4 (kchunk 320)
    gemm_v2_kernel<64, 128, 4, 8><<<dim3((POI + 127) / 128, 1, 4), 256>>>(
        g_oc_p, fc_w, nullptr, g_pt_p, BATCH, POI, CATDIM, 320);
    reduce_bias_kernel<<<(BATCH * POI + 255) / 256, 256>>>(
        g_pt_p, fc_b, out_logits, BATCH * POI, POI, 4);
}

// round 6
// speedup vs baseline: 3.8449x; 1.0431x over previous
#include <cuda_runtime.h>
#include <math.h>

#define POI   5000
#define EMB   256
#define UNITS 512
#define QDIM  256
#define BATCH 64
#define X1DIM  (EMB + QDIM)        // 512
#define CATDIM (EMB + 2 * UNITS)   // 1280
#define NCH    10                  // context p-chunks (5000/10 = 500)

// ---------------- scratch (no cudaMalloc allowed) ----------------
__device__ float g_h[BATCH * UNITS];
__device__ float g_qproj[BATCH * UNITS];
__device__ float g_vproj[POI * UNITS];            // 10.24 MB
__device__ float g_score[BATCH * POI];
__device__ float g_ctxpart[NCH * BATCH * EMB];
__device__ float g_outcat[BATCH * CATDIM];
__device__ float g_part[10 * BATCH * POI];        // partial slabs (12.8 MB max: fc S=10)

__device__ __forceinline__ float tanh_ap(float x) {
    float y;
    asm("tanh.approx.f32 %0, %1;" : "=f"(y) : "f"(x));
    return y;
}

// ---------------- gemm_v2: C[M,N] = A[M,K] @ W[K,N] (+bias iff gridDim.z==1) -----
// BK=32, block=256 threads = 16(r) x 16(c); thread computes TM x TN.
// grid (N/BN, ceil(M/BM), S). S>1 -> writes partial slab z (no bias).
template <int BM, int BN, int TM, int TN>
__global__ void gemm_v2_kernel(const float* __restrict__ A,
                               const float* __restrict__ W,
                               const float* __restrict__ bias,
                               float* __restrict__ out,
                               int M, int N, int K, int kchunk) {
    __shared__ float As[32][BM + 1];   // As[k][m]
    __shared__ float Ws[32][BN];       // Ws[k][n]
    const int tid = threadIdx.x;
    const int r = tid >> 4;
    const int c = tid & 15;
    const int n0 = blockIdx.x * BN;
    const int m0 = blockIdx.y * BM;
    const int kbase = blockIdx.z * kchunk;

    float acc[TM][TN];
#pragma unroll
    for (int i = 0; i < TM; i++)
#pragma unroll
        for (int j = 0; j < TN; j++) acc[i][j] = 0.f;

    for (int kk = kbase; kk < kbase + kchunk; kk += 32) {
#pragma unroll
        for (int pass = 0; pass < (BM * 32) / 1024; pass++) {
            int idx = pass * 1024 + tid * 4;
            int m = idx >> 5;
            int k = idx & 31;
            float4 v = make_float4(0.f, 0.f, 0.f, 0.f);
            if (m0 + m < M) v = *(const float4*)(A + (size_t)(m0 + m) * K + kk + k);
            As[k + 0][m] = v.x;
            As[k + 1][m] = v.y;
            As[k + 2][m] = v.z;
            As[k + 3][m] = v.w;
        }
#pragma unroll
        for (int pass = 0; pass < (32 * BN) / 1024; pass++) {
            int idx = pass * 1024 + tid * 4;
            int k = idx / BN;
            int n = idx % BN;
            float4 v = make_float4(0.f, 0.f, 0.f, 0.f);
            if (n0 + n < N) v = *(const float4*)(W + (size_t)(kk + k) * N + n0 + n);
            *(float4*)&Ws[k][n] = v;
        }
        __syncthreads();
#pragma unroll
        for (int k = 0; k < 32; k++) {
            float a[TM];
#pragma unroll
            for (int i = 0; i < TM; i++) a[i] = As[k][r * TM + i];
            float b[TN];
#pragma unroll
            for (int j = 0; j < TN; j += 4)
                *(float4*)&b[j] = *(const float4*)&Ws[k][c * TN + j];
#pragma unroll
            for (int i = 0; i < TM; i++)
#pragma unroll
                for (int j = 0; j < TN; j++)
                    acc[i][j] = fmaf(a[i], b[j], acc[i][j]);
        }
        __syncthreads();
    }

    const bool direct = (gridDim.z == 1);
    float* dst = direct ? out : out + (size_t)blockIdx.z * M * N;
#pragma unroll
    for (int i = 0; i < TM; i++) {
        int m = m0 + r * TM + i;
        if (m >= M) continue;
#pragma unroll
        for (int j = 0; j < TN; j += 4) {
            int n = n0 + c * TN + j;
            if (n < N) {
                float4 v;
                v.x = acc[i][j + 0] + (direct ? bias[n + 0] : 0.f);
                v.y = acc[i][j + 1] + (direct ? bias[n + 1] : 0.f);
                v.z = acc[i][j + 2] + (direct ? bias[n + 2] : 0.f);
                v.w = acc[i][j + 3] + (direct ? bias[n + 3] : 0.f);
                *(float4*)(dst + (size_t)m * N + n) = v;
            }
        }
    }
}

// ---------------- merged GRU matmuls: slabs 0..7 = xm (x1 built inline), 8..15 = hm
// grid (24, 1, 16), block 256. BM=64, BN=64, TM=TN=4, kchunk=64.
__global__ void gru_mm_kernel(const int* __restrict__ x,
                              const float* __restrict__ query,
                              const float* __restrict__ emb,
                              const float* __restrict__ dec_hidden,
                              const float* __restrict__ Wk,
                              const float* __restrict__ Wr,
                              float* __restrict__ part) {
    const int NN = 3 * UNITS;
    __shared__ float As[32][65];
    __shared__ float Ws[32][64];
    const int tid = threadIdx.x;
    const int r = tid >> 4;
    const int c = tid & 15;
    const int n0 = blockIdx.x * 64;
    const bool isX = blockIdx.z < 8;
    const int kbase = (isX ? blockIdx.z : blockIdx.z - 8) * 64;
    const float* W = isX ? Wk : Wr;

    float acc[4][4];
#pragma unroll
    for (int i = 0; i < 4; i++)
#pragma unroll
        for (int j = 0; j < 4; j++) acc[i][j] = 0.f;

    for (int kk = kbase; kk < kbase + 64; kk += 32) {
#pragma unroll
        for (int pass = 0; pass < 2; pass++) {
            int idx = pass * 1024 + tid * 4;
            int m = idx >> 5;
            int k = idx & 31;
            int gk = kk + k;
            float4 v;
            if (isX) {
                if (gk < EMB)
                    v = *(const float4*)(emb + (size_t)x[m] * EMB + gk);
                else
                    v = *(const float4*)(query + (size_t)m * QDIM + gk - EMB);
            } else {
                v = *(const float4*)(dec_hidden + (size_t)m * UNITS + gk);
            }
            As[k + 0][m] = v.x;
            As[k + 1][m] = v.y;
            As[k + 2][m] = v.z;
            As[k + 3][m] = v.w;
        }
#pragma unroll
        for (int pass = 0; pass < 2; pass++) {
            int idx = pass * 1024 + tid * 4;
            int k = idx >> 6;
            int n = idx & 63;
            *(float4*)&Ws[k][n] = *(const float4*)(W + (size_t)(kk + k) * NN + n0 + n);
        }
        __syncthreads();
#pragma unroll
        for (int k = 0; k < 32; k++) {
            float a0 = As[k][r * 4 + 0];
            float a1 = As[k][r * 4 + 1];
            float a2 = As[k][r * 4 + 2];
            float a3 = As[k][r * 4 + 3];
            float4 b = *(const float4*)&Ws[k][c * 4];
            acc[0][0] = fmaf(a0, b.x, acc[0][0]); acc[0][1] = fmaf(a0, b.y, acc[0][1]);
            acc[0][2] = fmaf(a0, b.z, acc[0][2]); acc[0][3] = fmaf(a0, b.w, acc[0][3]);
            acc[1][0] = fmaf(a1, b.x, acc[1][0]); acc[1][1] = fmaf(a1, b.y, acc[1][1]);
            acc[1][2] = fmaf(a1, b.z, acc[1][2]); acc[1][3] = fmaf(a1, b.w, acc[1][3]);
            acc[2][0] = fmaf(a2, b.x, acc[2][0]); acc[2][1] = fmaf(a2, b.y, acc[2][1]);
            acc[2][2] = fmaf(a2, b.z, acc[2][2]); acc[2][3] = fmaf(a2, b.w, acc[2][3]);
            acc[3][0] = fmaf(a3, b.x, acc[3][0]); acc[3][1] = fmaf(a3, b.y, acc[3][1]);
            acc[3][2] = fmaf(a3, b.z, acc[3][2]); acc[3][3] = fmaf(a3, b.w, acc[3][3]);
        }
        __syncthreads();
    }

    float* dst = part + (size_t)blockIdx.z * BATCH * NN;
#pragma unroll
    for (int i = 0; i < 4; i++) {
        int m = r * 4 + i;
#pragma unroll
        for (int j = 0; j < 4; j += 4) {
            int n = n0 + c * 4 + j;
            float4 v = make_float4(acc[i][0], acc[i][1], acc[i][2], acc[i][3]);
            *(float4*)(dst + (size_t)m * NN + n) = v;
        }
    }
}

// ---------------- reduce K-split partials + bias ----------------
__global__ void reduce_bias_kernel(const float* __restrict__ part,
                                   const float* __restrict__ bias,
                                   float* __restrict__ C,
                                   int MN, int N, int S) {
    int i = blockIdx.x * 256 + threadIdx.x;
    if (i >= MN) return;
    float s = 0.f;
    for (int z = 0; z < S; z++) s += part[(size_t)z * MN + i];
    C[i] = s + bias[i % N];
}

// ---------------- GRU gates: sums 8 xm slabs + 8 hm slabs + bias ----------------
__global__ void gru_gates_kernel(const float* __restrict__ part,
                                 const float* __restrict__ bias,
                                 const float* __restrict__ h_in,
                                 float* __restrict__ h_scratch,
                                 float* __restrict__ out_state,
                                 float* __restrict__ out_output) {
    const int NN = 3 * UNITS;
    int b = blockIdx.x;
    int u = threadIdx.x;               // 512
    float xz = bias[u], xr = bias[UNITS + u], xh = bias[2 * UNITS + u];
    float hz = bias[NN + u], hr = bias[NN + UNITS + u], hh = bias[NN + 2 * UNITS + u];
#pragma unroll
    for (int z = 0; z < 8; z++) {
        const float* px = part + (size_t)z * BATCH * NN + b * NN;
        const float* ph = part + (size_t)(8 + z) * BATCH * NN + b * NN;
        xz += px[u]; xr += px[UNITS + u]; xh += px[2 * UNITS + u];
        hz += ph[u]; hr += ph[UNITS + u]; hh += ph[2 * UNITS + u];
    }
    float z = 1.f / (1.f + expf(-(xz + hz)));
    float r = 1.f / (1.f + expf(-(xr + hr)));
    float hc = tanhf(xh + r * hh);
    float h = h_in[b * UNITS + u];
    float hn = z * h + (1.f - z) * hc;
    h_scratch[b * UNITS + u] = hn;
    if (out_state)  out_state[b * UNITS + u] = hn;
    if (out_output) out_output[b * UNITS + u] = hn;
}

// ---------------- attention score, 4 batch rows per block (proven R5) -----------
__global__ void attn_score_kernel(const float* __restrict__ vproj,
                                  const float* __restrict__ qproj,
                                  const float* __restrict__ Vw,
                                  const float* __restrict__ Vb,
                                  float* __restrict__ score) {
    __shared__ float q_s[4][UNITS];
    __shared__ float vw_s[UNITS];
    __shared__ float v_s[128][33];
    const int tid = threadIdx.x;       // 128
    const int p0 = blockIdx.x * 128;
    const int b0 = blockIdx.y * 4;

    for (int t = tid; t < 4 * UNITS; t += 128) {
        int b = t >> 9, u = t & 511;
        q_s[b][u] = qproj[(b0 + b) * UNITS + u];
    }
    for (int t = tid; t < UNITS; t += 128) vw_s[t] = Vw[t];

    float acc0 = 0.f, acc1 = 0.f, acc2 = 0.f, acc3 = 0.f;
    for (int u0 = 0; u0 < UNITS; u0 += 32) {
        __syncthreads();
        for (int t = tid; t < 128 * 32; t += 128) {
            int p = t >> 5, j = t & 31;
            v_s[p][j] = (p0 + p < POI) ? vproj[(p0 + p) * UNITS + u0 + j] : 0.f;
        }
        __syncthreads();
#pragma unroll
        for (int j = 0; j < 32; ++j) {
            float v  = v_s[tid][j];
            float vw = vw_s[u0 + j];
            acc0 = fmaf(vw, tanh_ap(v + q_s[0][u0 + j]), acc0);
            acc1 = fmaf(vw, tanh_ap(v + q_s[1][u0 + j]), acc1);
            acc2 = fmaf(vw, tanh_ap(v + q_s[2][u0 + j]), acc2);
            acc3 = fmaf(vw, tanh_ap(v + q_s[3][u0 + j]), acc3);
        }
    }
    if (p0 + tid < POI) {
        float vb = Vb[0];
        score[(b0 + 0) * POI + p0 + tid] = acc0 + vb;
        score[(b0 + 1) * POI + p0 + tid] = acc1 + vb;
        score[(b0 + 2) * POI + p0 + tid] = acc2 + vb;
        score[(b0 + 3) * POI + p0 + tid] = acc3 + vb;
    }
}

// ---------------- softmax over POI per batch row (in place) ----------------
__global__ void softmax_rows_kernel(float* __restrict__ score) {
    int b = blockIdx.x;
    int tid = threadIdx.x;             // 256
    __shared__ float red[256];
    float m = -1e30f;
    for (int p = tid; p < POI; p += 256) m = fmaxf(m, score[b * POI + p]);
    red[tid] = m;
    __syncthreads();
    for (int s = 128; s > 0; s >>= 1) {
        if (tid < s) red[tid] = fmaxf(red[tid], red[tid + s]);
        __syncthreads();
    }
    m = red[0];
    __syncthreads();
    float sum = 0.f;
    for (int p = tid; p < POI; p += 256) {
        float e = __expf(score[b * POI + p] - m);
        score[b * POI + p] = e;
        sum += e;
    }
    red[tid] = sum;
    __syncthreads();
    for (int s = 128; s > 0; s >>= 1) {
        if (tid < s) red[tid] += red[tid + s];
        __syncthreads();
    }
    float inv = 1.f / red[0];
    for (int p = tid; p < POI; p += 256) score[b * POI + p] *= inv;
}

// ---------------- context partials: 4 batch rows per block, NCH p-chunks --------
__global__ void context_partial_kernel(const float* __restrict__ attn,
                                       const float* __restrict__ emb,
                                       float* __restrict__ part) {
    const int PC = POI / NCH;          // 500
    int b0 = blockIdx.x * 4;
    int ch = blockIdx.y;
    int e  = threadIdx.x;              // 256 == EMB
    int p0 = ch * PC;
    const float* a0 = attn + (b0 + 0) * POI;
    const float* a1 = attn + (b0 + 1) * POI;
    const float* a2 = attn + (b0 + 2) * POI;
    const float* a3 = attn + (b0 + 3) * POI;
    float c0 = 0.f, c1 = 0.f, c2 = 0.f, c3 = 0.f;
#pragma unroll 4
    for (int p = p0; p < p0 + PC; ++p) {
        float ev = emb[p * EMB + e];
        c0 = fmaf(a0[p], ev, c0);
        c1 = fmaf(a1[p], ev, c1);
        c2 = fmaf(a2[p], ev, c2);
        c3 = fmaf(a3[p], ev, c3);
    }
    part[(ch * BATCH + b0 + 0) * EMB + e] = c0;
    part[(ch * BATCH + b0 + 1) * EMB + e] = c1;
    part[(ch * BATCH + b0 + 2) * EMB + e] = c2;
    part[(ch * BATCH + b0 + 3) * EMB + e] = c3;
}

// ---------------- outcat = [sum(ctx partials) | h | cat_dec] ----------------
__global__ void build_outcat_kernel(const float* __restrict__ part,
                                    const float* __restrict__ h,
                                    const float* __restrict__ cat_dec,
                                    float* __restrict__ outcat) {
    int b = blockIdx.x;
    int e = threadIdx.x;               // 256
    float s = 0.f;
#pragma unroll
    for (int ch = 0; ch < NCH; ch++) s += part[(ch * BATCH + b) * EMB + e];
    outcat[b * CATDIM + e] = s;
    for (int c = e; c < UNITS; c += 256) {
        outcat[b * CATDIM + EMB + c]         = h[b * UNITS + c];
        outcat[b * CATDIM + EMB + UNITS + c] = cat_dec[b * UNITS + c];
    }
}

// ---------------- launch ----------------
extern "C" void kernel_launch(void* const* d_in, const int* in_sizes, int n_in,
                              void* d_out, int out_size) {
    const int*   x          = (const int*)  d_in[0];
    const float* query      = (const float*)d_in[1];
    const float* emb        = (const float*)d_in[2];
    // d_in[3] = A_hat (unused)
    const float* dec_hidden = (const float*)d_in[4];
    const float* cat_dec    = (const float*)d_in[5];
    const float* gru_kernel = (const float*)d_in[6];
    const float* gru_rec    = (const float*)d_in[7];
    const float* gru_bias   = (const float*)d_in[8];
    const float* W1_w       = (const float*)d_in[9];
    const float* W1_b       = (const float*)d_in[10];
    const float* W2_w       = (const float*)d_in[11];
    const float* W2_b       = (const float*)d_in[12];
    const float* V_w        = (const float*)d_in[13];
    const float* V_b        = (const float*)d_in[14];
    const float* fc_w       = (const float*)d_in[15];
    const float* fc_b       = (const float*)d_in[16];

    float* out        = (float*)d_out;
    float* out_logits = out;
    float* out_state  = (out_size >= BATCH * POI + BATCH * UNITS)
                        ? out + BATCH * POI : nullptr;
    float* out_output = (out_size >= BATCH * POI + 2 * BATCH * UNITS)
                        ? out + BATCH * POI + BATCH * UNITS : nullptr;

    float *g_h_p, *g_qp_p, *g_vp_p, *g_sc_p, *g_cp_p, *g_oc_p, *g_pt_p;
    cudaGetSymbolAddress((void**)&g_h_p,  g_h);
    cudaGetSymbolAddress((void**)&g_qp_p, g_qproj);
    cudaGetSymbolAddress((void**)&g_vp_p, g_vproj);
    cudaGetSymbolAddress((void**)&g_sc_p, g_score);
    cudaGetSymbolAddress((void**)&g_cp_p, g_ctxpart);
    cudaGetSymbolAddress((void**)&g_oc_p, g_outcat);
    cudaGetSymbolAddress((void**)&g_pt_p, g_part);

    // v_proj = emb @ W1 + b : M=5000, N=512, K=256 (direct)
    gemm_v2_kernel<128, 64, 8, 4><<<dim3(UNITS / 64, (POI + 127) / 128, 1), 256>>>(
        emb, W1_w, W1_b, g_vp_p, POI, UNITS, EMB, EMB);

    // GRU: merged xm (slabs 0..7, x1 built inline) + hm (slabs 8..15)
    gru_mm_kernel<<<dim3(3 * UNITS / 64, 1, 16), 256>>>(
        x, query, emb, dec_hidden, gru_kernel, gru_rec, g_pt_p);
    gru_gates_kernel<<<BATCH, UNITS>>>(g_pt_p, gru_bias, dec_hidden,
                                       g_h_p, out_state, out_output);

    // q_proj = h @ W2 + b : K=512 split 8
    gemm_v2_kernel<64, 64, 4, 4><<<dim3(UNITS / 64, 1, 8), 256>>>(
        g_h_p, W2_w, nullptr, g_pt_p, BATCH, UNITS, UNITS, 64);
    reduce_bias_kernel<<<(BATCH * UNITS + 255) / 256, 256>>>(
        g_pt_p, W2_b, g_qp_p, BATCH * UNITS, UNITS, 8);

    // attention
    attn_score_kernel<<<dim3((POI + 127) / 128, BATCH / 4), 128>>>(
        g_vp_p, g_qp_p, V_w, V_b, g_sc_p);
    softmax_rows_kernel<<<BATCH, 256>>>(g_sc_p);
    context_partial_kernel<<<dim3(BATCH / 4, NCH), 256>>>(g_sc_p, emb, g_cp_p);
    build_outcat_kernel<<<BATCH, 256>>>(g_cp_p, g_h_p, cat_dec, g_oc_p);

    // logits = outcat @ fc_w + fc_b : N=5000, K=1280 split 10 (kchunk 128)
    gemm_v2_kernel<64, 128, 4, 8><<<dim3((POI + 127) / 128, 1, 10), 256>>>(
        g_oc_p, fc_w, nullptr, g_pt_p, BATCH, POI, CATDIM, 128);
    reduce_bias_kernel<<<(BATCH * POI + 255) / 256, 256>>>(
        g_pt_p, fc_b, out_logits, BATCH * POI, POI, 10);
}